// round 15
// baseline (speedup 1.0000x reference)
#include <cuda_runtime.h>
#include <cuda_bf16.h>
#include <cstdint>

// B=2, M=2048, HID=1024, NH=16, D=64.  Reference has NO softmax =>
//   G_b = h_b^T h_b (symmetric);  T_b = Wk G_b;  S_bh = T_h Wv_h^T;
//   U_b[:,hD:+D] = Wq_h^T S_bh;  Ct_b = Wo U_b^T;  out_b = h_b Ct_b^T.
// Inner GEMMs: mma.sync bf16x3 (A*B ~= Ah*Bh + Ah*Bl + Al*Bh).
// Final GEMM (out): int8 IMMA m16n8k32, 2-limb row-scaled decomposition:
//   x = s*(x0 + x1/254);  D = sA*sB*(d00 + (d01+d10)/254)  (3 IMMA per k32
//   = half the tensor instructions of bf16x3).
// (tcgen05 rejected by harness's compute_103 PTX target.)

#define HIDD   1024
#define MSEQ   2048
#define NBATCH 2
#define NHEAD  16
#define DHEAD  64

typedef __nv_bfloat16 bf16;

// ---------------- device scratch ----------------
__device__ bf16 g_hTh[NBATCH * HIDD * MSEQ], g_hTl[NBATCH * HIDD * MSEQ];
__device__ bf16 g_wkh[HIDD * HIDD], g_wkl[HIDD * HIDD];
__device__ bf16 g_woh[HIDD * HIDD], g_wol[HIDD * HIDD];
__device__ float g_Gp[4 * HIDD * HIDD];               // [s*2+b] fp32 partials
__device__ bf16 g_Gh[NBATCH * HIDD * HIDD], g_Gl[NBATCH * HIDD * HIDD];
__device__ float g_T[NBATCH * HIDD * HIDD];
__device__ float g_S[NBATCH * NHEAD * DHEAD * DHEAD];
__device__ bf16 g_Uh[NBATCH * HIDD * HIDD], g_Ul[NBATCH * HIDD * HIDD];
__device__ float g_Ctf[NBATCH * HIDD * HIDD];
// int8 limbs + row scales for the final GEMM
__device__ int8_t g_h0[NBATCH * MSEQ * HIDD], g_h1[NBATCH * MSEQ * HIDD];
__device__ float  g_sh[NBATCH * MSEQ];
__device__ int8_t g_c0[NBATCH * HIDD * HIDD], g_c1[NBATCH * HIDD * HIDD];
__device__ float  g_sc[NBATCH * HIDD];

// ---------------- helpers ----------------
__device__ __forceinline__ void split2(float x, bf16& hi, bf16& lo) {
    hi = __float2bfloat16(x);
    lo = __float2bfloat16(x - __bfloat162float(hi));
}

__device__ __forceinline__ uint32_t swz(uint32_t off) {
    return off ^ ((off >> 3) & 0x30);
}

__device__ __forceinline__ void ldsm4(uint32_t* r, uint32_t sa) {
    asm volatile("ldmatrix.sync.aligned.m8n8.x4.shared.b16 {%0,%1,%2,%3}, [%4];"
                 : "=r"(r[0]), "=r"(r[1]), "=r"(r[2]), "=r"(r[3]) : "r"(sa));
}

__device__ __forceinline__ void mma_bf16(float* d, const uint32_t* a,
                                         uint32_t b0, uint32_t b1) {
    asm volatile(
        "mma.sync.aligned.m16n8k16.row.col.f32.bf16.bf16.f32 "
        "{%0,%1,%2,%3}, {%4,%5,%6,%7}, {%8,%9}, {%0,%1,%2,%3};"
        : "+f"(d[0]), "+f"(d[1]), "+f"(d[2]), "+f"(d[3])
        : "r"(a[0]), "r"(a[1]), "r"(a[2]), "r"(a[3]), "r"(b0), "r"(b1));
}

__device__ __forceinline__ void mma_s8(int* d, const uint32_t* a,
                                       uint32_t b0, uint32_t b1) {
    asm volatile(
        "mma.sync.aligned.m16n8k32.row.col.s32.s8.s8.s32 "
        "{%0,%1,%2,%3}, {%4,%5,%6,%7}, {%8,%9}, {%0,%1,%2,%3};"
        : "+r"(d[0]), "+r"(d[1]), "+r"(d[2]), "+r"(d[3])
        : "r"(a[0]), "r"(a[1]), "r"(a[2]), "r"(a[3]), "r"(b0), "r"(b1));
}

__device__ __forceinline__ void cp16(uint32_t d, const void* s) {
    asm volatile("cp.async.cg.shared.global [%0], [%1], 16;" :: "r"(d), "l"(s));
}

// ---------------- split fp32 -> (hi, lo) bf16 planes ----------------
__global__ __launch_bounds__(256)
void split_kernel(const float4* __restrict__ x, __nv_bfloat162* __restrict__ hi,
                  __nv_bfloat162* __restrict__ lo, int n4) {
    int i = blockIdx.x * 256 + threadIdx.x;
    if (i >= n4) return;
    float4 v = x[i];
    bf16 h0, l0, h1, l1, h2, l2, h3, l3;
    split2(v.x, h0, l0); split2(v.y, h1, l1);
    split2(v.z, h2, l2); split2(v.w, h3, l3);
    hi[2 * i]     = __nv_bfloat162(h0, h1);
    hi[2 * i + 1] = __nv_bfloat162(h2, h3);
    lo[2 * i]     = __nv_bfloat162(l0, l1);
    lo[2 * i + 1] = __nv_bfloat162(l2, l3);
}

// ---------------- transpose + split: h[b][m][k] -> hT planes [b][k][m] -----
__global__ __launch_bounds__(256)
void tsplit_kernel(const float* __restrict__ h) {
    __shared__ float t[32][33];
    const int b = blockIdx.z;
    const int k0 = blockIdx.x * 32, m0 = blockIdx.y * 32;
    const int col = threadIdx.x & 31, rr = threadIdx.x >> 5;

    const float* hp = h + ((size_t)b * MSEQ + m0) * HIDD + k0;
#pragma unroll
    for (int s = 0; s < 4; s++)
        t[rr + s * 8][col] = hp[(size_t)(rr + s * 8) * HIDD + col];
    __syncthreads();

    const size_t ob = ((size_t)b * HIDD + k0) * MSEQ + m0;
#pragma unroll
    for (int s = 0; s < 4; s++) {
        int kr = rr + s * 8;
        bf16 hi, lo;
        split2(t[col][kr], hi, lo);
        g_hTh[ob + (size_t)kr * MSEQ + col] = hi;
        g_hTl[ob + (size_t)kr * MSEQ + col] = lo;
    }
}

// ---------------- quantize: fp32 rows(1024) -> 2x int8 limbs + row scale ----
// x = s*(x0 + x1/254), s = rowmax/127.  grid = rows, 256 threads.
__global__ __launch_bounds__(256)
void quant_kernel(const float* __restrict__ x, char4* __restrict__ q0,
                  char4* __restrict__ q1, float* __restrict__ sc) {
    __shared__ float red[8];
    const int row = blockIdx.x;
    const int tid = threadIdx.x;
    const float4 v = ((const float4*)(x + (size_t)row * 1024))[tid];

    float m = fmaxf(fmaxf(fabsf(v.x), fabsf(v.y)), fmaxf(fabsf(v.z), fabsf(v.w)));
#pragma unroll
    for (int o = 16; o > 0; o >>= 1)
        m = fmaxf(m, __shfl_xor_sync(0xFFFFFFFFu, m, o));
    if ((tid & 31) == 0) red[tid >> 5] = m;
    __syncthreads();
    float mall = red[0];
#pragma unroll
    for (int i = 1; i < 8; i++) mall = fmaxf(mall, red[i]);

    const float rs = (mall > 0.0f) ? 127.0f / mall : 0.0f;
    if (tid == 0) sc[row] = (mall > 0.0f) ? mall / 127.0f : 0.0f;

    float q, f0;
    char c0[4], c1[4];
    const float* pv = (const float*)&v;
#pragma unroll
    for (int i = 0; i < 4; i++) {
        q = pv[i] * rs;
        f0 = rintf(q);
        c0[i] = (char)(int)f0;
        c1[i] = (char)(int)rintf((q - f0) * 254.0f);
    }
    q0[(size_t)row * 256 + tid] = make_char4(c0[0], c0[1], c0[2], c0[3]);
    q1[(size_t)row * 256 + tid] = make_char4(c1[0], c1[1], c1[2], c1[3]);
}

// ---------------- bf16x3 mma.sync GEMM: D[128x128 tile] = A * B^T ----------
#define TILE_B 8192
#define BUF_B  (4 * TILE_B)
#define DSM_SIZE (2 * BUF_B + 256)

__device__ __forceinline__ void stage(uint32_t sb, const bf16* g, int ld, int tid) {
#pragma unroll
    for (int i = 0; i < 2; i++) {
        int idx = tid + 256 * i;
        int r = idx >> 2;
        int c = (idx & 3) * 16;
        cp16(sb + swz((uint32_t)(r * 64 + c)),
             (const char*)g + (size_t)r * (ld * 2) + c);
    }
}

template <bool OSPLIT>
__global__ __launch_bounds__(256, 2)
void gemm3(const bf16* __restrict__ Ah, const bf16* __restrict__ Al,
           const bf16* __restrict__ Bh, const bf16* __restrict__ Bl,
           float* __restrict__ Cf, bf16* __restrict__ Ch, bf16* __restrict__ Cl,
           int K, int ldA, int ldB, int ldC, size_t sA, size_t sB, size_t sC,
           int tri_mode, int zmode)
{
    extern __shared__ char dyn[];
    uint32_t dbase = (uint32_t)__cvta_generic_to_shared(dyn);
    dbase = (dbase + 255u) & ~255u;

    if (zmode == 1) {
        size_t o = (size_t)(blockIdx.z & 1) * sA + (size_t)(blockIdx.z >> 1) * 1024;
        Ah += o; Al += o; Bh += o; Bl += o;
        Cf += (size_t)blockIdx.z * sC;
    } else {
        Ah += (size_t)blockIdx.z * sA;  Al += (size_t)blockIdx.z * sA;
        Bh += (size_t)blockIdx.z * sB;  Bl += (size_t)blockIdx.z * sB;
        if (OSPLIT) { Ch += (size_t)blockIdx.z * sC; Cl += (size_t)blockIdx.z * sC; }
        else        { Cf += (size_t)blockIdx.z * sC; }
    }

    int bm, bn;
    if (tri_mode) {
        int t = blockIdx.x, i = 0;
        while (t >= 8 - i) { t -= 8 - i; i++; }
        bm = i * 128; bn = (i + t) * 128;
    } else {
        bm = blockIdx.y * 128; bn = blockIdx.x * 128;
    }

    const int tid = threadIdx.x;
    const int lane = tid & 31;
    const int wid = tid >> 5;
    const int wm = (wid >> 2) * 64;
    const int wn = (wid & 3) * 32;

    float acc[4][4][4];
#pragma unroll
    for (int mi = 0; mi < 4; mi++)
#pragma unroll
        for (int ni = 0; ni < 4; ni++)
#pragma unroll
            for (int r = 0; r < 4; r++) acc[mi][ni][r] = 0.0f;

    const bf16* Am  = Ah + (size_t)bm * ldA;
    const bf16* Alm = Al + (size_t)bm * ldA;
    const bf16* Bm  = Bh + (size_t)bn * ldB;
    const bf16* Blm = Bl + (size_t)bn * ldB;

    const int NIT = K / 32;

    stage(dbase,              Am,  ldA, tid);
    stage(dbase + TILE_B,     Alm, ldA, tid);
    stage(dbase + 2 * TILE_B, Bm,  ldB, tid);
    stage(dbase + 3 * TILE_B, Blm, ldB, tid);
    asm volatile("cp.async.commit_group;" ::: "memory");

    for (int it = 0; it < NIT; it++) {
        if (it + 1 < NIT) {
            const uint32_t bo = dbase + ((it + 1) & 1) * BUF_B;
            const int k0 = (it + 1) * 32;
            stage(bo,              Am + k0,  ldA, tid);
            stage(bo + TILE_B,     Alm + k0, ldA, tid);
            stage(bo + 2 * TILE_B, Bm + k0,  ldB, tid);
            stage(bo + 3 * TILE_B, Blm + k0, ldB, tid);
            asm volatile("cp.async.commit_group;" ::: "memory");
            asm volatile("cp.async.wait_group 1;" ::: "memory");
        } else {
            asm volatile("cp.async.wait_group 0;" ::: "memory");
        }
        __syncthreads();

        const uint32_t bo = dbase + (it & 1) * BUF_B;
        const int rlane = lane & 15;
        const int kbyte = (lane >> 4) * 16;
#pragma unroll
        for (int kk = 0; kk < 2; kk++) {
            const uint32_t cbyte = kk * 32 + kbyte;
            uint32_t bH[2][4], bL[2][4];
#pragma unroll
            for (int nb = 0; nb < 2; nb++) {
                uint32_t off = (uint32_t)((wn + nb * 16 + rlane) * 64) + cbyte;
                ldsm4(bH[nb], bo + 2 * TILE_B + swz(off));
                ldsm4(bL[nb], bo + 3 * TILE_B + swz(off));
            }
#pragma unroll
            for (int half = 0; half < 2; half++) {
                uint32_t aH[2][4], aL[2][4];
#pragma unroll
                for (int m2 = 0; m2 < 2; m2++) {
                    uint32_t off =
                        (uint32_t)((wm + (half * 2 + m2) * 16 + rlane) * 64) + cbyte;
                    ldsm4(aH[m2], bo + swz(off));
                    ldsm4(aL[m2], bo + TILE_B + swz(off));
                }
#pragma unroll
                for (int m2 = 0; m2 < 2; m2++)
#pragma unroll
                    for (int ni = 0; ni < 4; ni++) {
                        const int nb = ni >> 1, sub = ni & 1;
                        mma_bf16(acc[half * 2 + m2][ni], aH[m2],
                                 bH[nb][sub], bH[nb][sub + 2]);
                    }
#pragma unroll
                for (int m2 = 0; m2 < 2; m2++)
#pragma unroll
                    for (int ni = 0; ni < 4; ni++) {
                        const int nb = ni >> 1, sub = ni & 1;
                        mma_bf16(acc[half * 2 + m2][ni], aH[m2],
                                 bL[nb][sub], bL[nb][sub + 2]);
                    }
#pragma unroll
                for (int m2 = 0; m2 < 2; m2++)
#pragma unroll
                    for (int ni = 0; ni < 4; ni++) {
                        const int nb = ni >> 1, sub = ni & 1;
                        mma_bf16(acc[half * 2 + m2][ni], aL[m2],
                                 bH[nb][sub], bH[nb][sub + 2]);
                    }
            }
        }
        __syncthreads();
    }

    const int g = lane >> 2;
    const int c2 = (lane & 3) * 2;
#pragma unroll
    for (int mi = 0; mi < 4; mi++) {
#pragma unroll
        for (int ni = 0; ni < 4; ni++) {
            int row0 = bm + wm + mi * 16 + g;
            int col  = bn + wn + ni * 8 + c2;
            float* a = acc[mi][ni];
            if (OSPLIT) {
                bf16 h0, l0, h1, l1;
                split2(a[0], h0, l0); split2(a[1], h1, l1);
                *(__nv_bfloat162*)(Ch + (size_t)row0 * ldC + col) = __nv_bfloat162(h0, h1);
                *(__nv_bfloat162*)(Cl + (size_t)row0 * ldC + col) = __nv_bfloat162(l0, l1);
                split2(a[2], h0, l0); split2(a[3], h1, l1);
                *(__nv_bfloat162*)(Ch + (size_t)(row0 + 8) * ldC + col) = __nv_bfloat162(h0, h1);
                *(__nv_bfloat162*)(Cl + (size_t)(row0 + 8) * ldC + col) = __nv_bfloat162(l0, l1);
            } else {
                *(float2*)(Cf + (size_t)row0 * ldC + col)       = make_float2(a[0], a[1]);
                *(float2*)(Cf + (size_t)(row0 + 8) * ldC + col) = make_float2(a[2], a[3]);
            }
        }
    }
}

// ---------------- int8 2-limb GEMM: out_b[m,n] = sum_k h[m,k]*Ct[n,k] ------
// A limbs g_h0/g_h1 rows of 1024B, B limbs g_c0/g_c1. BK=64 bytes.
// d00 -> acc0, (d01 + d10) -> acc1;  out = sA*sB*(acc0 + acc1/254).
__device__ __forceinline__ void stage8(uint32_t sb, const int8_t* g, int ldb, int tid) {
#pragma unroll
    for (int i = 0; i < 2; i++) {
        int idx = tid + 256 * i;
        int r = idx >> 2;
        int c = (idx & 3) * 16;
        cp16(sb + swz((uint32_t)(r * 64 + c)), g + (size_t)r * ldb + c);
    }
}

__global__ __launch_bounds__(256)
void gemm_s8_out(float* __restrict__ out)
{
    extern __shared__ char dyn[];
    uint32_t dbase = (uint32_t)__cvta_generic_to_shared(dyn);
    dbase = (dbase + 255u) & ~255u;

    const int b = blockIdx.z;
    const int bm = blockIdx.y * 128;
    const int bn = blockIdx.x * 128;

    const int8_t* A0 = g_h0 + ((size_t)b * MSEQ + bm) * HIDD;
    const int8_t* A1 = g_h1 + ((size_t)b * MSEQ + bm) * HIDD;
    const int8_t* B0 = g_c0 + ((size_t)b * HIDD + bn) * HIDD;
    const int8_t* B1 = g_c1 + ((size_t)b * HIDD + bn) * HIDD;
    const float* scA = g_sh + (size_t)b * MSEQ;
    const float* scB = g_sc + (size_t)b * HIDD;
    out += (size_t)b * MSEQ * HIDD;

    const int tid = threadIdx.x;
    const int lane = tid & 31;
    const int wid = tid >> 5;
    const int wm = (wid >> 2) * 64;
    const int wn = (wid & 3) * 32;

    int acc0[4][4][4], acc1[4][4][4];
#pragma unroll
    for (int mi = 0; mi < 4; mi++)
#pragma unroll
        for (int ni = 0; ni < 4; ni++)
#pragma unroll
            for (int r = 0; r < 4; r++) { acc0[mi][ni][r] = 0; acc1[mi][ni][r] = 0; }

    const int NIT = HIDD / 64;   // 16

    stage8(dbase,              A0, HIDD, tid);
    stage8(dbase + TILE_B,     A1, HIDD, tid);
    stage8(dbase + 2 * TILE_B, B0, HIDD, tid);
    stage8(dbase + 3 * TILE_B, B1, HIDD, tid);
    asm volatile("cp.async.commit_group;" ::: "memory");

    for (int it = 0; it < NIT; it++) {
        if (it + 1 < NIT) {
            const uint32_t bo = dbase + ((it + 1) & 1) * BUF_B;
            const int k0 = (it + 1) * 64;
            stage8(bo,              A0 + k0, HIDD, tid);
            stage8(bo + TILE_B,     A1 + k0, HIDD, tid);
            stage8(bo + 2 * TILE_B, B0 + k0, HIDD, tid);
            stage8(bo + 3 * TILE_B, B1 + k0, HIDD, tid);
            asm volatile("cp.async.commit_group;" ::: "memory");
            asm volatile("cp.async.wait_group 1;" ::: "memory");
        } else {
            asm volatile("cp.async.wait_group 0;" ::: "memory");
        }
        __syncthreads();

        const uint32_t bo = dbase + (it & 1) * BUF_B;
        const int rlane = lane & 15;
        const int kbyte = (lane >> 4) * 16;
#pragma unroll
        for (int kk = 0; kk < 2; kk++) {         // two k32 steps (32B each)
            const uint32_t cbyte = kk * 32 + kbyte;
            uint32_t b0f[2][4], b1f[2][4];
#pragma unroll
            for (int nb = 0; nb < 2; nb++) {
                uint32_t off = (uint32_t)((wn + nb * 16 + rlane) * 64) + cbyte;
                ldsm4(b0f[nb], bo + 2 * TILE_B + swz(off));
                ldsm4(b1f[nb], bo + 3 * TILE_B + swz(off));
            }
#pragma unroll
            for (int half = 0; half < 2; half++) {
                uint32_t a0f[2][4], a1f[2][4];
#pragma unroll
                for (int m2 = 0; m2 < 2; m2++) {
                    uint32_t off =
                        (uint32_t)((wm + (half * 2 + m2) * 16 + rlane) * 64) + cbyte;
                    ldsm4(a0f[m2], bo + swz(off));
                    ldsm4(a1f[m2], bo + TILE_B + swz(off));
                }
#pragma unroll
                for (int m2 = 0; m2 < 2; m2++)
#pragma unroll
                    for (int ni = 0; ni < 4; ni++) {
                        const int nb = ni >> 1, sub = ni & 1;
                        mma_s8(acc0[half * 2 + m2][ni], a0f[m2],
                               b0f[nb][sub], b0f[nb][sub + 2]);
                    }
#pragma unroll
                for (int m2 = 0; m2 < 2; m2++)
#pragma unroll
                    for (int ni = 0; ni < 4; ni++) {
                        const int nb = ni >> 1, sub = ni & 1;
                        mma_s8(acc1[half * 2 + m2][ni], a0f[m2],
                               b1f[nb][sub], b1f[nb][sub + 2]);
                    }
#pragma unroll
                for (int m2 = 0; m2 < 2; m2++)
#pragma unroll
                    for (int ni = 0; ni < 4; ni++) {
                        const int nb = ni >> 1, sub = ni & 1;
                        mma_s8(acc1[half * 2 + m2][ni], a1f[m2],
                               b0f[nb][sub], b0f[nb][sub + 2]);
                    }
            }
        }
        __syncthreads();
    }

    const int g = lane >> 2;
    const int c2 = (lane & 3) * 2;
    const float inv254 = 1.0f / 254.0f;
#pragma unroll
    for (int mi = 0; mi < 4; mi++) {
#pragma unroll
        for (int ni = 0; ni < 4; ni++) {
            int row0 = bm + wm + mi * 16 + g;
            int col  = bn + wn + ni * 8 + c2;
            float sb0 = scB[col], sb1 = scB[col + 1];
            float sa0 = scA[row0], sa1 = scA[row0 + 8];
            int* a0 = acc0[mi][ni];
            int* a1 = acc1[mi][ni];
            *(float2*)(out + (size_t)row0 * HIDD + col) = make_float2(
                sa0 * sb0 * ((float)a0[0] + (float)a1[0] * inv254),
                sa0 * sb1 * ((float)a0[1] + (float)a1[1] * inv254));
            *(float2*)(out + (size_t)(row0 + 8) * HIDD + col) = make_float2(
                sa1 * sb0 * ((float)a0[2] + (float)a1[2] * inv254),
                sa1 * sb1 * ((float)a0[3] + (float)a1[3] * inv254));
        }
    }
}

// ---------------- G combine: sum split-K partials, bf16 planes, mirror -----
#define GCOMB_SMEM (128 * 129 * 4)
__global__ __launch_bounds__(256)
void gcomb_kernel()
{
    extern __shared__ float ts[];
    const int b = blockIdx.y;
    int t = blockIdx.x, i = 0;
    while (t >= 8 - i) { t -= 8 - i; i++; }
    const int j = i + t;
    const size_t HH = (size_t)HIDD * HIDD;
    const int tid = threadIdx.x;

    const float* p0 = g_Gp + (size_t)b * HH       + (size_t)(i * 128) * HIDD + j * 128;
    const float* p1 = g_Gp + (size_t)(2 + b) * HH + (size_t)(i * 128) * HIDD + j * 128;

    for (int idx = tid; idx < 128 * 32; idx += 256) {
        int r = idx >> 5, c4 = (idx & 31) * 4;
        float4 a = *(const float4*)(p0 + (size_t)r * HIDD + c4);
        float4 c = *(const float4*)(p1 + (size_t)r * HIDD + c4);
        ts[r * 129 + c4 + 0] = a.x + c.x;
        ts[r * 129 + c4 + 1] = a.y + c.y;
        ts[r * 129 + c4 + 2] = a.z + c.z;
        ts[r * 129 + c4 + 3] = a.w + c.w;
    }
    __syncthreads();

    bf16* Gh = g_Gh + (size_t)b * HH;
    bf16* Gl = g_Gl + (size_t)b * HH;

    {
        const size_t base = (size_t)(i * 128) * HIDD + j * 128;
        for (int idx = tid; idx < 128 * 64; idx += 256) {
            int r = idx >> 6, c2 = (idx & 63) * 2;
            bf16 h0, l0, h1, l1;
            split2(ts[r * 129 + c2], h0, l0);
            split2(ts[r * 129 + c2 + 1], h1, l1);
            *(__nv_bfloat162*)(Gh + base + (size_t)r * HIDD + c2) = __nv_bfloat162(h0, h1);
            *(__nv_bfloat162*)(Gl + base + (size_t)r * HIDD + c2) = __nv_bfloat162(l0, l1);
        }
    }
    if (i != j) {
        const size_t base = (size_t)(j * 128) * HIDD + i * 128;
        for (int idx = tid; idx < 128 * 64; idx += 256) {
            int r = idx >> 6, c2 = (idx & 63) * 2;
            bf16 h0, l0, h1, l1;
            split2(ts[c2 * 129 + r], h0, l0);
            split2(ts[(c2 + 1) * 129 + r], h1, l1);
            *(__nv_bfloat162*)(Gh + base + (size_t)r * HIDD + c2) = __nv_bfloat162(h0, h1);
            *(__nv_bfloat162*)(Gl + base + (size_t)r * HIDD + c2) = __nv_bfloat162(l0, l1);
        }
    }
}

// ---------------- S: S_bh[i,j] = sum_q T_b[h*64+i,q] * Wv[h*64+j,q] --------
__global__ __launch_bounds__(256)
void st_kernel(const float* __restrict__ Wv)
{
    const int bh = blockIdx.x;
    const int b = bh >> 4, h = bh & 15;
    const float* Tp = g_T + (size_t)b * HIDD * HIDD + (size_t)(h * DHEAD) * HIDD;
    const float* Wp = Wv + (size_t)(h * DHEAD) * HIDD;

    __shared__ float Ts[32][68];
    __shared__ float Ws[32][68];

    const int tid = threadIdx.x;
    const int i4 = (tid & 15) * 4, j4 = (tid >> 4) * 4;

    float acc[4][4];
#pragma unroll
    for (int i = 0; i < 4; i++)
#pragma unroll
        for (int j = 0; j < 4; j++) acc[i][j] = 0.0f;

    for (int k0 = 0; k0 < HIDD; k0 += 32) {
#pragma unroll
        for (int s = 0; s < 2; s++) {
            int idx = tid + 256 * s;
            int i = idx >> 3;
            int c4 = (idx & 7) * 4;
            float4 tv = *(const float4*)(Tp + (size_t)i * HIDD + k0 + c4);
            Ts[c4 + 0][i] = tv.x; Ts[c4 + 1][i] = tv.y;
            Ts[c4 + 2][i] = tv.z; Ts[c4 + 3][i] = tv.w;
            float4 wv = *(const float4*)(Wp + (size_t)i * HIDD + k0 + c4);
            Ws[c4 + 0][i] = wv.x; Ws[c4 + 1][i] = wv.y;
            Ws[c4 + 2][i] = wv.z; Ws[c4 + 3][i] = wv.w;
        }
        __syncthreads();
#pragma unroll 8
        for (int kk = 0; kk < 32; kk++) {
            float tf[4], vf[4];
            *(float4*)tf = *(const float4*)&Ts[kk][i4];
            *(float4*)vf = *(const float4*)&Ws[kk][j4];
#pragma unroll
            for (int i = 0; i < 4; i++)
#pragma unroll
                for (int j = 0; j < 4; j++) acc[i][j] += tf[i] * vf[j];
        }
        __syncthreads();
    }

    float* Sp = g_S + (size_t)bh * (DHEAD * DHEAD);
#pragma unroll
    for (int i = 0; i < 4; i++)
        *(float4*)(Sp + (size_t)(i4 + i) * DHEAD + j4) =
            make_float4(acc[i][0], acc[i][1], acc[i][2], acc[i][3]);
}

// ---------------- U: U[b][k][h*64+j] = sum_i Wq[h*64+i][k]*S_bh[i][j] ------
__global__ __launch_bounds__(256)
void u_kernel(const float* __restrict__ Wq)
{
    const int bh = blockIdx.x;
    const int b = bh >> 4, h = bh & 15;
    const int k = blockIdx.y * 256 + threadIdx.x;
    const int j0 = blockIdx.z * 32;

    __shared__ float Ss[DHEAD][32];
    for (int e = threadIdx.x; e < DHEAD * 32; e += 256) {
        int i = e >> 5, j = e & 31;
        Ss[i][j] = g_S[(size_t)bh * (DHEAD * DHEAD) + i * DHEAD + j0 + j];
    }
    __syncthreads();

    float acc[32];
#pragma unroll
    for (int j = 0; j < 32; j++) acc[j] = 0.0f;

#pragma unroll 4
    for (int i = 0; i < DHEAD; i++) {
        float w = Wq[(size_t)(h * DHEAD + i) * HIDD + k];
#pragma unroll
        for (int j = 0; j < 32; j += 4) {
            float4 sv = *(const float4*)&Ss[i][j];
            acc[j + 0] += w * sv.x; acc[j + 1] += w * sv.y;
            acc[j + 2] += w * sv.z; acc[j + 3] += w * sv.w;
        }
    }

    size_t base = ((size_t)b * HIDD + k) * HIDD + h * DHEAD + j0;
#pragma unroll
    for (int j = 0; j < 32; j += 2) {
        bf16 h0, l0, h1, l1;
        split2(acc[j], h0, l0); split2(acc[j + 1], h1, l1);
        *(__nv_bfloat162*)(g_Uh + base + j) = __nv_bfloat162(h0, h1);
        *(__nv_bfloat162*)(g_Ul + base + j) = __nv_bfloat162(l0, l1);
    }
}

// ---------------- launch ----------------
extern "C" void kernel_launch(void* const* d_in, const int* in_sizes, int n_in,
                              void* d_out, int out_size)
{
    const float* h  = (const float*)d_in[0];
    // d_in[1] = key_pe: dead branch in reference, unused.
    const float* Wq = (const float*)d_in[2];
    const float* Wk = (const float*)d_in[3];
    const float* Wv = (const float*)d_in[4];
    const float* Wo = (const float*)d_in[5];
    float* out = (float*)d_out;

    bf16 *hTh, *hTl, *wkh, *wkl, *woh, *wol, *Gh, *Gl, *Uh, *Ul;
    float *Gpp, *Tp, *Ctf, *sh, *sc;
    int8_t *h0, *h1, *c0, *c1;
    cudaGetSymbolAddress((void**)&hTh, g_hTh); cudaGetSymbolAddress((void**)&hTl, g_hTl);
    cudaGetSymbolAddress((void**)&wkh, g_wkh); cudaGetSymbolAddress((void**)&wkl, g_wkl);
    cudaGetSymbolAddress((void**)&woh, g_woh); cudaGetSymbolAddress((void**)&wol, g_wol);
    cudaGetSymbolAddress((void**)&Gpp, g_Gp);
    cudaGetSymbolAddress((void**)&Gh, g_Gh);   cudaGetSymbolAddress((void**)&Gl, g_Gl);
    cudaGetSymbolAddress((void**)&Tp, g_T);
    cudaGetSymbolAddress((void**)&Uh, g_Uh);   cudaGetSymbolAddress((void**)&Ul, g_Ul);
    cudaGetSymbolAddress((void**)&Ctf, g_Ctf);
    cudaGetSymbolAddress((void**)&h0, g_h0);   cudaGetSymbolAddress((void**)&h1, g_h1);
    cudaGetSymbolAddress((void**)&c0, g_c0);   cudaGetSymbolAddress((void**)&c1, g_c1);
    cudaGetSymbolAddress((void**)&sh, g_sh);   cudaGetSymbolAddress((void**)&sc, g_sc);

    cudaFuncSetAttribute(gemm3<false>, cudaFuncAttributeMaxDynamicSharedMemorySize, DSM_SIZE);
    cudaFuncSetAttribute(gemm3<true>,  cudaFuncAttributeMaxDynamicSharedMemorySize, DSM_SIZE);
    cudaFuncSetAttribute(gemm_s8_out,  cudaFuncAttributeMaxDynamicSharedMemorySize, DSM_SIZE);
    cudaFuncSetAttribute(gcomb_kernel, cudaFuncAttributeMaxDynamicSharedMemorySize, GCOMB_SMEM);

    const dim3 blk(256);
    const size_t HH = (size_t)HIDD * HIDD;
    const size_t MH = (size_t)MSEQ * HIDD;
    const int nw4 = (HIDD * HIDD) / 4;

    // input prep
    quant_kernel<<<NBATCH * MSEQ, blk>>>(h, (char4*)h0, (char4*)h1, sh);
    tsplit_kernel<<<dim3(HIDD / 32, MSEQ / 32, NBATCH), blk>>>(h);
    split_kernel<<<(nw4 + 255) / 256, blk>>>((const float4*)Wk,
        (__nv_bfloat162*)wkh, (__nv_bfloat162*)wkl, nw4);
    split_kernel<<<(nw4 + 255) / 256, blk>>>((const float4*)Wo,
        (__nv_bfloat162*)woh, (__nv_bfloat162*)wol, nw4);

    // G partials: triangular tiles (36), z = s*2+b (split-K 2 x 1024), fp32
    gemm3<false><<<dim3(36, 1, 4), blk, DSM_SIZE>>>(
        hTh, hTl, hTh, hTl, Gpp, nullptr, nullptr,
        1024, MSEQ, MSEQ, HIDD, MH, MH, HH, /*tri=*/1, /*zmode=*/1);

    gcomb_kernel<<<dim3(36, NBATCH), blk, GCOMB_SMEM>>>();

    // T_b = Wk * G_b (G symmetric => A*B^T form) -> fp32
    gemm3<false><<<dim3(HIDD / 128, HIDD / 128, NBATCH), blk, DSM_SIZE>>>(
        wkh, wkl, Gh, Gl, Tp, nullptr, nullptr,
        HIDD, HIDD, HIDD, HIDD, 0, HH, HH, 0, 0);

    st_kernel<<<dim3(NBATCH * NHEAD), blk>>>(Wv);
    u_kernel<<<dim3(NBATCH * NHEAD, HIDD / 256, 2), blk>>>(Wq);

    // Ct_b[n,k] = sum_j Wo[n,j] U_b[k,j] -> fp32
    gemm3<false><<<dim3(HIDD / 128, HIDD / 128, NBATCH), blk, DSM_SIZE>>>(
        woh, wol, Uh, Ul, Ctf, nullptr, nullptr,
        HIDD, HIDD, HIDD, HIDD, 0, HH, HH, 0, 0);

    // quantize Ct rows -> int8 limbs
    quant_kernel<<<NBATCH * HIDD, blk>>>(Ctf, (char4*)c0, (char4*)c1, sc);

    // out_b[m,n] = sum_k h[m,k] Ct[n,k]  (int8 2-limb IMMA)
    gemm_s8_out<<<dim3(HIDD / 128, MSEQ / 128, NBATCH), blk, DSM_SIZE>>>(out);
}

// round 16
// speedup vs baseline: 1.4237x; 1.4237x over previous
#include <cuda_runtime.h>
#include <cuda_bf16.h>
#include <cstdint>

// B=2, M=2048, HID=1024, NH=16, D=64.  Reference has NO softmax =>
//   G_b = h_b^T h_b (symmetric);  T_b = Wk G_b;  S_bh = T_h Wv_h^T;
//   U_b[:,hD:+D] = Wq_h^T S_bh;  Ct_b = Wo U_b^T;  out_b = h_b Ct_b^T.
// G computed triangular (36 tiles) + split-K(2).  All big GEMMs are
// D = A * B^T, K-major, mma.sync bf16x3 (A*B ~= Ah*Bh + Ah*Bl + Al*Bh).
// (tcgen05 rejected by harness's compute_103 target; int8 IMMA measured
// slower per MAC on the sm_103 fallback path in R15 -> reverted.)
// This round: out GEMM re-tiled 64x64 for wave balance (256 units over
// 148 SMs was 2-wave-imbalanced); h plane-split fused into tsplit.

#define HIDD   1024
#define MSEQ   2048
#define NBATCH 2
#define NHEAD  16
#define DHEAD  64

typedef __nv_bfloat16 bf16;

// ---------------- device scratch ----------------
__device__ bf16 g_hh[NBATCH * MSEQ * HIDD], g_hl[NBATCH * MSEQ * HIDD];
__device__ bf16 g_hTh[NBATCH * HIDD * MSEQ], g_hTl[NBATCH * HIDD * MSEQ];
__device__ bf16 g_wkh[HIDD * HIDD], g_wkl[HIDD * HIDD];
__device__ bf16 g_woh[HIDD * HIDD], g_wol[HIDD * HIDD];
__device__ float g_Gp[4 * HIDD * HIDD];               // [s*2+b] fp32 partials
__device__ bf16 g_Gh[NBATCH * HIDD * HIDD], g_Gl[NBATCH * HIDD * HIDD];
__device__ float g_T[NBATCH * HIDD * HIDD];
__device__ float g_S[NBATCH * NHEAD * DHEAD * DHEAD];
__device__ bf16 g_Uh[NBATCH * HIDD * HIDD], g_Ul[NBATCH * HIDD * HIDD];
__device__ bf16 g_Cth[NBATCH * HIDD * HIDD], g_Ctl[NBATCH * HIDD * HIDD];

// ---------------- helpers ----------------
__device__ __forceinline__ void split2(float x, bf16& hi, bf16& lo) {
    hi = __float2bfloat16(x);
    lo = __float2bfloat16(x - __bfloat162float(hi));
}

__device__ __forceinline__ uint32_t swz(uint32_t off) {
    return off ^ ((off >> 3) & 0x30);
}

__device__ __forceinline__ void ldsm4(uint32_t* r, uint32_t sa) {
    asm volatile("ldmatrix.sync.aligned.m8n8.x4.shared.b16 {%0,%1,%2,%3}, [%4];"
                 : "=r"(r[0]), "=r"(r[1]), "=r"(r[2]), "=r"(r[3]) : "r"(sa));
}

__device__ __forceinline__ void mma_bf16(float* d, const uint32_t* a,
                                         uint32_t b0, uint32_t b1) {
    asm volatile(
        "mma.sync.aligned.m16n8k16.row.col.f32.bf16.bf16.f32 "
        "{%0,%1,%2,%3}, {%4,%5,%6,%7}, {%8,%9}, {%0,%1,%2,%3};"
        : "+f"(d[0]), "+f"(d[1]), "+f"(d[2]), "+f"(d[3])
        : "r"(a[0]), "r"(a[1]), "r"(a[2]), "r"(a[3]), "r"(b0), "r"(b1));
}

__device__ __forceinline__ void cp16(uint32_t d, const void* s) {
    asm volatile("cp.async.cg.shared.global [%0], [%1], 16;" :: "r"(d), "l"(s));
}

// ---------------- split fp32 -> (hi, lo) bf16 planes ----------------
__global__ __launch_bounds__(256)
void split_kernel(const float4* __restrict__ x, __nv_bfloat162* __restrict__ hi,
                  __nv_bfloat162* __restrict__ lo, int n4) {
    int i = blockIdx.x * 256 + threadIdx.x;
    if (i >= n4) return;
    float4 v = x[i];
    bf16 h0, l0, h1, l1, h2, l2, h3, l3;
    split2(v.x, h0, l0); split2(v.y, h1, l1);
    split2(v.z, h2, l2); split2(v.w, h3, l3);
    hi[2 * i]     = __nv_bfloat162(h0, h1);
    hi[2 * i + 1] = __nv_bfloat162(h2, h3);
    lo[2 * i]     = __nv_bfloat162(l0, l1);
    lo[2 * i + 1] = __nv_bfloat162(l2, l3);
}

// ------- transpose + split: h -> hT planes [b][k][m] AND h planes ----------
__global__ __launch_bounds__(256)
void tsplit_kernel(const float* __restrict__ h) {
    __shared__ float t[32][33];
    const int b = blockIdx.z;
    const int k0 = blockIdx.x * 32, m0 = blockIdx.y * 32;
    const int col = threadIdx.x & 31, rr = threadIdx.x >> 5;

    const float* hp = h + ((size_t)b * MSEQ + m0) * HIDD + k0;
#pragma unroll
    for (int s = 0; s < 4; s++)
        t[rr + s * 8][col] = hp[(size_t)(rr + s * 8) * HIDD + col];
    __syncthreads();

    // non-transposed planes (row = m, col = k): coalesced on col
    const size_t nb = ((size_t)b * MSEQ + m0) * HIDD + k0;
#pragma unroll
    for (int s = 0; s < 4; s++) {
        int mr = rr + s * 8;
        bf16 hi, lo;
        split2(t[mr][col], hi, lo);
        g_hh[nb + (size_t)mr * HIDD + col] = hi;
        g_hl[nb + (size_t)mr * HIDD + col] = lo;
    }
    // transposed planes (row = k, col = m)
    const size_t ob = ((size_t)b * HIDD + k0) * MSEQ + m0;
#pragma unroll
    for (int s = 0; s < 4; s++) {
        int kr = rr + s * 8;
        bf16 hi, lo;
        split2(t[col][kr], hi, lo);
        g_hTh[ob + (size_t)kr * MSEQ + col] = hi;
        g_hTl[ob + (size_t)kr * MSEQ + col] = lo;
    }
}

// ---------------- bf16x3 mma.sync GEMM: D[128x128 tile] = A * B^T ----------
// 2-stage cp.async pipeline, BK=32, 8 warps, warp tile 64x32, 2 CTAs/SM.
#define TILE_B 8192
#define BUF_B  (4 * TILE_B)
#define DSM_SIZE (2 * BUF_B + 256)

__device__ __forceinline__ void stage(uint32_t sb, const bf16* g, int ld, int tid) {
#pragma unroll
    for (int i = 0; i < 2; i++) {
        int idx = tid + 256 * i;
        int r = idx >> 2;
        int c = (idx & 3) * 16;
        cp16(sb + swz((uint32_t)(r * 64 + c)),
             (const char*)g + (size_t)r * (ld * 2) + c);
    }
}

template <bool OSPLIT>
__global__ __launch_bounds__(256, 2)
void gemm3(const bf16* __restrict__ Ah, const bf16* __restrict__ Al,
           const bf16* __restrict__ Bh, const bf16* __restrict__ Bl,
           float* __restrict__ Cf, bf16* __restrict__ Ch, bf16* __restrict__ Cl,
           int K, int ldA, int ldB, int ldC, size_t sA, size_t sB, size_t sC,
           int tri_mode, int zmode)
{
    extern __shared__ char dyn[];
    uint32_t dbase = (uint32_t)__cvta_generic_to_shared(dyn);
    dbase = (dbase + 255u) & ~255u;

    if (zmode == 1) {
        size_t o = (size_t)(blockIdx.z & 1) * sA + (size_t)(blockIdx.z >> 1) * 1024;
        Ah += o; Al += o; Bh += o; Bl += o;
        Cf += (size_t)blockIdx.z * sC;
    } else {
        Ah += (size_t)blockIdx.z * sA;  Al += (size_t)blockIdx.z * sA;
        Bh += (size_t)blockIdx.z * sB;  Bl += (size_t)blockIdx.z * sB;
        if (OSPLIT) { Ch += (size_t)blockIdx.z * sC; Cl += (size_t)blockIdx.z * sC; }
        else        { Cf += (size_t)blockIdx.z * sC; }
    }

    int bm, bn;
    if (tri_mode) {
        int t = blockIdx.x, i = 0;
        while (t >= 8 - i) { t -= 8 - i; i++; }
        bm = i * 128; bn = (i + t) * 128;
    } else {
        bm = blockIdx.y * 128; bn = blockIdx.x * 128;
    }

    const int tid = threadIdx.x;
    const int lane = tid & 31;
    const int wid = tid >> 5;
    const int wm = (wid >> 2) * 64;
    const int wn = (wid & 3) * 32;

    float acc[4][4][4];
#pragma unroll
    for (int mi = 0; mi < 4; mi++)
#pragma unroll
        for (int ni = 0; ni < 4; ni++)
#pragma unroll
            for (int r = 0; r < 4; r++) acc[mi][ni][r] = 0.0f;

    const bf16* Am  = Ah + (size_t)bm * ldA;
    const bf16* Alm = Al + (size_t)bm * ldA;
    const bf16* Bm  = Bh + (size_t)bn * ldB;
    const bf16* Blm = Bl + (size_t)bn * ldB;

    const int NIT = K / 32;

    stage(dbase,              Am,  ldA, tid);
    stage(dbase + TILE_B,     Alm, ldA, tid);
    stage(dbase + 2 * TILE_B, Bm,  ldB, tid);
    stage(dbase + 3 * TILE_B, Blm, ldB, tid);
    asm volatile("cp.async.commit_group;" ::: "memory");

    for (int it = 0; it < NIT; it++) {
        if (it + 1 < NIT) {
            const uint32_t bo = dbase + ((it + 1) & 1) * BUF_B;
            const int k0 = (it + 1) * 32;
            stage(bo,              Am + k0,  ldA, tid);
            stage(bo + TILE_B,     Alm + k0, ldA, tid);
            stage(bo + 2 * TILE_B, Bm + k0,  ldB, tid);
            stage(bo + 3 * TILE_B, Blm + k0, ldB, tid);
            asm volatile("cp.async.commit_group;" ::: "memory");
            asm volatile("cp.async.wait_group 1;" ::: "memory");
        } else {
            asm volatile("cp.async.wait_group 0;" ::: "memory");
        }
        __syncthreads();

        const uint32_t bo = dbase + (it & 1) * BUF_B;
        const int rlane = lane & 15;
        const int kbyte = (lane >> 4) * 16;
#pragma unroll
        for (int kk = 0; kk < 2; kk++) {
            const uint32_t cbyte = kk * 32 + kbyte;
            uint32_t bH[2][4], bL[2][4];
#pragma unroll
            for (int nb = 0; nb < 2; nb++) {
                uint32_t off = (uint32_t)((wn + nb * 16 + rlane) * 64) + cbyte;
                ldsm4(bH[nb], bo + 2 * TILE_B + swz(off));
                ldsm4(bL[nb], bo + 3 * TILE_B + swz(off));
            }
#pragma unroll
            for (int half = 0; half < 2; half++) {
                uint32_t aH[2][4], aL[2][4];
#pragma unroll
                for (int m2 = 0; m2 < 2; m2++) {
                    uint32_t off =
                        (uint32_t)((wm + (half * 2 + m2) * 16 + rlane) * 64) + cbyte;
                    ldsm4(aH[m2], bo + swz(off));
                    ldsm4(aL[m2], bo + TILE_B + swz(off));
                }
#pragma unroll
                for (int m2 = 0; m2 < 2; m2++)
#pragma unroll
                    for (int ni = 0; ni < 4; ni++) {
                        const int nb = ni >> 1, sub = ni & 1;
                        mma_bf16(acc[half * 2 + m2][ni], aH[m2],
                                 bH[nb][sub], bH[nb][sub + 2]);
                    }
#pragma unroll
                for (int m2 = 0; m2 < 2; m2++)
#pragma unroll
                    for (int ni = 0; ni < 4; ni++) {
                        const int nb = ni >> 1, sub = ni & 1;
                        mma_bf16(acc[half * 2 + m2][ni], aH[m2],
                                 bL[nb][sub], bL[nb][sub + 2]);
                    }
#pragma unroll
                for (int m2 = 0; m2 < 2; m2++)
#pragma unroll
                    for (int ni = 0; ni < 4; ni++) {
                        const int nb = ni >> 1, sub = ni & 1;
                        mma_bf16(acc[half * 2 + m2][ni], aL[m2],
                                 bH[nb][sub], bH[nb][sub + 2]);
                    }
            }
        }
        __syncthreads();
    }

    const int g = lane >> 2;
    const int c2 = (lane & 3) * 2;
#pragma unroll
    for (int mi = 0; mi < 4; mi++) {
#pragma unroll
        for (int ni = 0; ni < 4; ni++) {
            int row0 = bm + wm + mi * 16 + g;
            int col  = bn + wn + ni * 8 + c2;
            float* a = acc[mi][ni];
            if (OSPLIT) {
                bf16 h0, l0, h1, l1;
                split2(a[0], h0, l0); split2(a[1], h1, l1);
                *(__nv_bfloat162*)(Ch + (size_t)row0 * ldC + col) = __nv_bfloat162(h0, h1);
                *(__nv_bfloat162*)(Cl + (size_t)row0 * ldC + col) = __nv_bfloat162(l0, l1);
                split2(a[2], h0, l0); split2(a[3], h1, l1);
                *(__nv_bfloat162*)(Ch + (size_t)(row0 + 8) * ldC + col) = __nv_bfloat162(h0, h1);
                *(__nv_bfloat162*)(Cl + (size_t)(row0 + 8) * ldC + col) = __nv_bfloat162(l0, l1);
            } else {
                *(float2*)(Cf + (size_t)row0 * ldC + col)       = make_float2(a[0], a[1]);
                *(float2*)(Cf + (size_t)(row0 + 8) * ldC + col) = make_float2(a[2], a[3]);
            }
        }
    }
}

// ------- out GEMM, 64x64 tiles for wave balance: out_b = h_b * Ct_b^T ------
// 1024 CTAs of 13.5 SM-us each -> ceil(1024/148)=7 granules = ~94.5us
// (vs 108us with 256 full tiles).  8 warps as 2(M) x 4(N), warp tile 32x16.
#define TILE64_B 4096
#define BUF64_B  (4 * TILE64_B)
#define DSM64    (2 * BUF64_B + 256)

__device__ __forceinline__ void stage64(uint32_t sb, const bf16* g, int tid) {
    int r = tid >> 2;            // 0..63
    int c = (tid & 3) * 16;      // 0,16,32,48
    cp16(sb + swz((uint32_t)(r * 64 + c)),
         (const char*)g + (size_t)r * (HIDD * 2) + c);
}

__global__ __launch_bounds__(256)
void gemm_out64(float* __restrict__ out)
{
    extern __shared__ char dyn[];
    uint32_t dbase = (uint32_t)__cvta_generic_to_shared(dyn);
    dbase = (dbase + 255u) & ~255u;

    const int b = blockIdx.z;
    const int bm = blockIdx.y * 64;
    const int bn = blockIdx.x * 64;

    const bf16* Am  = g_hh  + ((size_t)b * MSEQ + bm) * HIDD;
    const bf16* Alm = g_hl  + ((size_t)b * MSEQ + bm) * HIDD;
    const bf16* Bm  = g_Cth + ((size_t)b * HIDD + bn) * HIDD;
    const bf16* Blm = g_Ctl + ((size_t)b * HIDD + bn) * HIDD;
    out += (size_t)b * MSEQ * HIDD;

    const int tid = threadIdx.x;
    const int lane = tid & 31;
    const int wid = tid >> 5;
    const int wm = (wid >> 2) * 32;   // 0, 32
    const int wn = (wid & 3) * 16;    // 0,16,32,48

    float acc[2][2][4];
#pragma unroll
    for (int mi = 0; mi < 2; mi++)
#pragma unroll
        for (int ni = 0; ni < 2; ni++)
#pragma unroll
            for (int r = 0; r < 4; r++) acc[mi][ni][r] = 0.0f;

    const int NIT = HIDD / 32;   // 32

    stage64(dbase,                Am,  tid);
    stage64(dbase + TILE64_B,     Alm, tid);
    stage64(dbase + 2 * TILE64_B, Bm,  tid);
    stage64(dbase + 3 * TILE64_B, Blm, tid);
    asm volatile("cp.async.commit_group;" ::: "memory");

    for (int it = 0; it < NIT; it++) {
        if (it + 1 < NIT) {
            const uint32_t bo = dbase + ((it + 1) & 1) * BUF64_B;
            const int k0 = (it + 1) * 32;
            stage64(bo,                Am + k0,  tid);
            stage64(bo + TILE64_B,     Alm + k0, tid);
            stage64(bo + 2 * TILE64_B, Bm + k0,  tid);
            stage64(bo + 3 * TILE64_B, Blm + k0, tid);
            asm volatile("cp.async.commit_group;" ::: "memory");
            asm volatile("cp.async.wait_group 1;" ::: "memory");
        } else {
            asm volatile("cp.async.wait_group 0;" ::: "memory");
        }
        __syncthreads();

        const uint32_t bo = dbase + (it & 1) * BUF64_B;
        const int rlane = lane & 15;
        const int kbyte = (lane >> 4) * 16;
#pragma unroll
        for (int kk = 0; kk < 2; kk++) {
            const uint32_t cbyte = kk * 32 + kbyte;
            uint32_t bH[4], bL[4], aH[2][4], aL[2][4];
            {
                uint32_t off = (uint32_t)((wn + rlane) * 64) + cbyte;
                ldsm4(bH, bo + 2 * TILE64_B + swz(off));
                ldsm4(bL, bo + 3 * TILE64_B + swz(off));
            }
#pragma unroll
            for (int mi = 0; mi < 2; mi++) {
                uint32_t off = (uint32_t)((wm + mi * 16 + rlane) * 64) + cbyte;
                ldsm4(aH[mi], bo + swz(off));
                ldsm4(aL[mi], bo + TILE64_B + swz(off));
            }
            // plane-major to keep accumulator revisits apart
#pragma unroll
            for (int mi = 0; mi < 2; mi++)
#pragma unroll
                for (int ni = 0; ni < 2; ni++)
                    mma_bf16(acc[mi][ni], aH[mi], bH[ni], bH[ni + 2]);
#pragma unroll
            for (int mi = 0; mi < 2; mi++)
#pragma unroll
                for (int ni = 0; ni < 2; ni++)
                    mma_bf16(acc[mi][ni], aH[mi], bL[ni], bL[ni + 2]);
#pragma unroll
            for (int mi = 0; mi < 2; mi++)
#pragma unroll
                for (int ni = 0; ni < 2; ni++)
                    mma_bf16(acc[mi][ni], aL[mi], bH[ni], bH[ni + 2]);
        }
        __syncthreads();
    }

    const int g = lane >> 2;
    const int c2 = (lane & 3) * 2;
#pragma unroll
    for (int mi = 0; mi < 2; mi++) {
#pragma unroll
        for (int ni = 0; ni < 2; ni++) {
            int row0 = bm + wm + mi * 16 + g;
            int col  = bn + wn + ni * 8 + c2;
            float* a = acc[mi][ni];
            *(float2*)(out + (size_t)row0 * HIDD + col)       = make_float2(a[0], a[1]);
            *(float2*)(out + (size_t)(row0 + 8) * HIDD + col) = make_float2(a[2], a[3]);
        }
    }
}

// ---------------- G combine: sum split-K partials, bf16 planes, mirror -----
#define GCOMB_SMEM (128 * 129 * 4)
__global__ __launch_bounds__(256)
void gcomb_kernel()
{
    extern __shared__ float ts[];
    const int b = blockIdx.y;
    int t = blockIdx.x, i = 0;
    while (t >= 8 - i) { t -= 8 - i; i++; }
    const int j = i + t;
    const size_t HH = (size_t)HIDD * HIDD;
    const int tid = threadIdx.x;

    const float* p0 = g_Gp + (size_t)b * HH       + (size_t)(i * 128) * HIDD + j * 128;
    const float* p1 = g_Gp + (size_t)(2 + b) * HH + (size_t)(i * 128) * HIDD + j * 128;

    for (int idx = tid; idx < 128 * 32; idx += 256) {
        int r = idx >> 5, c4 = (idx & 31) * 4;
        float4 a = *(const float4*)(p0 + (size_t)r * HIDD + c4);
        float4 c = *(const float4*)(p1 + (size_t)r * HIDD + c4);
        ts[r * 129 + c4 + 0] = a.x + c.x;
        ts[r * 129 + c4 + 1] = a.y + c.y;
        ts[r * 129 + c4 + 2] = a.z + c.z;
        ts[r * 129 + c4 + 3] = a.w + c.w;
    }
    __syncthreads();

    bf16* Gh = g_Gh + (size_t)b * HH;
    bf16* Gl = g_Gl + (size_t)b * HH;

    {
        const size_t base = (size_t)(i * 128) * HIDD + j * 128;
        for (int idx = tid; idx < 128 * 64; idx += 256) {
            int r = idx >> 6, c2 = (idx & 63) * 2;
            bf16 h0, l0, h1, l1;
            split2(ts[r * 129 + c2], h0, l0);
            split2(ts[r * 129 + c2 + 1], h1, l1);
            *(__nv_bfloat162*)(Gh + base + (size_t)r * HIDD + c2) = __nv_bfloat162(h0, h1);
            *(__nv_bfloat162*)(Gl + base + (size_t)r * HIDD + c2) = __nv_bfloat162(l0, l1);
        }
    }
    if (i != j) {
        const size_t base = (size_t)(j * 128) * HIDD + i * 128;
        for (int idx = tid; idx < 128 * 64; idx += 256) {
            int r = idx >> 6, c2 = (idx & 63) * 2;
            bf16 h0, l0, h1, l1;
            split2(ts[c2 * 129 + r], h0, l0);
            split2(ts[(c2 + 1) * 129 + r], h1, l1);
            *(__nv_bfloat162*)(Gh + base + (size_t)r * HIDD + c2) = __nv_bfloat162(h0, h1);
            *(__nv_bfloat162*)(Gl + base + (size_t)r * HIDD + c2) = __nv_bfloat162(l0, l1);
        }
    }
}

// ---------------- S: S_bh[i,j] = sum_q T_b[h*64+i,q] * Wv[h*64+j,q] --------
__global__ __launch_bounds__(256)
void st_kernel(const float* __restrict__ Wv)
{
    const int bh = blockIdx.x;
    const int b = bh >> 4, h = bh & 15;
    const float* Tp = g_T + (size_t)b * HIDD * HIDD + (size_t)(h * DHEAD) * HIDD;
    const float* Wp = Wv + (size_t)(h * DHEAD) * HIDD;

    __shared__ float Ts[32][68];
    __shared__ float Ws[32][68];

    const int tid = threadIdx.x;
    const int i4 = (tid & 15) * 4, j4 = (tid >> 4) * 4;

    float acc[4][4];
#pragma unroll
    for (int i = 0; i < 4; i++)
#pragma unroll
        for (int j = 0; j < 4; j++) acc[i][j] = 0.0f;

    for (int k0 = 0; k0 < HIDD; k0 += 32) {
#pragma unroll
        for (int s = 0; s < 2; s++) {
            int idx = tid + 256 * s;
            int i = idx >> 3;
            int c4 = (idx & 7) * 4;
            float4 tv = *(const float4*)(Tp + (size_t)i * HIDD + k0 + c4);
            Ts[c4 + 0][i] = tv.x; Ts[c4 + 1][i] = tv.y;
            Ts[c4 + 2][i] = tv.z; Ts[c4 + 3][i] = tv.w;
            float4 wv = *(const float4*)(Wp + (size_t)i * HIDD + k0 + c4);
            Ws[c4 + 0][i] = wv.x; Ws[c4 + 1][i] = wv.y;
            Ws[c4 + 2][i] = wv.z; Ws[c4 + 3][i] = wv.w;
        }
        __syncthreads();
#pragma unroll 8
        for (int kk = 0; kk < 32; kk++) {
            float tf[4], vf[4];
            *(float4*)tf = *(const float4*)&Ts[kk][i4];
            *(float4*)vf = *(const float4*)&Ws[kk][j4];
#pragma unroll
            for (int i = 0; i < 4; i++)
#pragma unroll
                for (int j = 0; j < 4; j++) acc[i][j] += tf[i] * vf[j];
        }
        __syncthreads();
    }

    float* Sp = g_S + (size_t)bh * (DHEAD * DHEAD);
#pragma unroll
    for (int i = 0; i < 4; i++)
        *(float4*)(Sp + (size_t)(i4 + i) * DHEAD + j4) =
            make_float4(acc[i][0], acc[i][1], acc[i][2], acc[i][3]);
}

// ---------------- U: U[b][k][h*64+j] = sum_i Wq[h*64+i][k]*S_bh[i][j] ------
__global__ __launch_bounds__(256)
void u_kernel(const float* __restrict__ Wq)
{
    const int bh = blockIdx.x;
    const int b = bh >> 4, h = bh & 15;
    const int k = blockIdx.y * 256 + threadIdx.x;
    const int j0 = blockIdx.z * 32;

    __shared__ float Ss[DHEAD][32];
    for (int e = threadIdx.x; e < DHEAD * 32; e += 256) {
        int i = e >> 5, j = e & 31;
        Ss[i][j] = g_S[(size_t)bh * (DHEAD * DHEAD) + i * DHEAD + j0 + j];
    }
    __syncthreads();

    float acc[32];
#pragma unroll
    for (int j = 0; j < 32; j++) acc[j] = 0.0f;

#pragma unroll 4
    for (int i = 0; i < DHEAD; i++) {
        float w = Wq[(size_t)(h * DHEAD + i) * HIDD + k];
#pragma unroll
        for (int j = 0; j < 32; j += 4) {
            float4 sv = *(const float4*)&Ss[i][j];
            acc[j + 0] += w * sv.x; acc[j + 1] += w * sv.y;
            acc[j + 2] += w * sv.z; acc[j + 3] += w * sv.w;
        }
    }

    size_t base = ((size_t)b * HIDD + k) * HIDD + h * DHEAD + j0;
#pragma unroll
    for (int j = 0; j < 32; j += 2) {
        bf16 h0, l0, h1, l1;
        split2(acc[j], h0, l0); split2(acc[j + 1], h1, l1);
        *(__nv_bfloat162*)(g_Uh + base + j) = __nv_bfloat162(h0, h1);
        *(__nv_bfloat162*)(g_Ul + base + j) = __nv_bfloat162(l0, l1);
    }
}

// ---------------- launch ----------------
extern "C" void kernel_launch(void* const* d_in, const int* in_sizes, int n_in,
                              void* d_out, int out_size)
{
    const float* h  = (const float*)d_in[0];
    // d_in[1] = key_pe: dead branch in reference, unused.
    const float* Wq = (const float*)d_in[2];
    const float* Wk = (const float*)d_in[3];
    const float* Wv = (const float*)d_in[4];
    const float* Wo = (const float*)d_in[5];
    float* out = (float*)d_out;

    bf16 *hTh, *hTl, *wkh, *wkl, *woh, *wol, *Gh, *Gl, *Uh, *Ul, *Cth, *Ctl;
    float *Gpp, *Tp;
    cudaGetSymbolAddress((void**)&hTh, g_hTh); cudaGetSymbolAddress((void**)&hTl, g_hTl);
    cudaGetSymbolAddress((void**)&wkh, g_wkh); cudaGetSymbolAddress((void**)&wkl, g_wkl);
    cudaGetSymbolAddress((void**)&woh, g_woh); cudaGetSymbolAddress((void**)&wol, g_wol);
    cudaGetSymbolAddress((void**)&Gpp, g_Gp);
    cudaGetSymbolAddress((void**)&Gh, g_Gh);   cudaGetSymbolAddress((void**)&Gl, g_Gl);
    cudaGetSymbolAddress((void**)&Tp, g_T);
    cudaGetSymbolAddress((void**)&Uh, g_Uh);   cudaGetSymbolAddress((void**)&Ul, g_Ul);
    cudaGetSymbolAddress((void**)&Cth, g_Cth); cudaGetSymbolAddress((void**)&Ctl, g_Ctl);

    cudaFuncSetAttribute(gemm3<false>, cudaFuncAttributeMaxDynamicSharedMemorySize, DSM_SIZE);
    cudaFuncSetAttribute(gemm3<true>,  cudaFuncAttributeMaxDynamicSharedMemorySize, DSM_SIZE);
    cudaFuncSetAttribute(gemm_out64,   cudaFuncAttributeMaxDynamicSharedMemorySize, DSM64);
    cudaFuncSetAttribute(gcomb_kernel, cudaFuncAttributeMaxDynamicSharedMemorySize, GCOMB_SMEM);

    const dim3 blk(256);
    const size_t HH = (size_t)HIDD * HIDD;
    const size_t MH = (size_t)MSEQ * HIDD;
    const int nw4 = (HIDD * HIDD) / 4;

    // input prep (tsplit also emits the non-transposed h planes)
    tsplit_kernel<<<dim3(HIDD / 32, MSEQ / 32, NBATCH), blk>>>(h);
    split_kernel<<<(nw4 + 255) / 256, blk>>>((const float4*)Wk,
        (__nv_bfloat162*)wkh, (__nv_bfloat162*)wkl, nw4);
    split_kernel<<<(nw4 + 255) / 256, blk>>>((const float4*)Wo,
        (__nv_bfloat162*)woh, (__nv_bfloat162*)wol, nw4);

    // G partials: triangular tiles (36), z = s*2+b (split-K 2 x 1024), fp32
    gemm3<false><<<dim3(36, 1, 4), blk, DSM_SIZE>>>(
        hTh, hTl, hTh, hTl, Gpp, nullptr, nullptr,
        1024, MSEQ, MSEQ, HIDD, MH, MH, HH, /*tri=*/1, /*zmode=*/1);

    // combine partials, split to bf16 planes, mirror lower triangle
    gcomb_kernel<<<dim3(36, NBATCH), blk, GCOMB_SMEM>>>();

    // T_b = Wk * G_b (G symmetric => A*B^T form) -> fp32
    gemm3<false><<<dim3(HIDD / 128, HIDD / 128, NBATCH), blk, DSM_SIZE>>>(
        wkh, wkl, Gh, Gl, Tp, nullptr, nullptr,
        HIDD, HIDD, HIDD, HIDD, 0, HH, HH, 0, 0);

    // S_bh = T_h * Wv_h^T (fp32, small)
    st_kernel<<<dim3(NBATCH * NHEAD), blk>>>(Wv);

    // U (fp32 compute, bf16 hi/lo planes out)
    u_kernel<<<dim3(NBATCH * NHEAD, HIDD / 256, 2), blk>>>(Wq);

    // Ct_b[n,k] = sum_j Wo[n,j] U_b[k,j] -> bf16 planes
    gemm3<true><<<dim3(HIDD / 128, HIDD / 128, NBATCH), blk, DSM_SIZE>>>(
        woh, wol, Uh, Ul, nullptr, Cth, Ctl,
        HIDD, HIDD, HIDD, HIDD, 0, HH, HH, 0, 0);

    // out_b[m,n] = sum_k h_b[m,k] Ct_b[n,k]  (64x64 tiles, wave-balanced)
    gemm_out64<<<dim3(HIDD / 64, MSEQ / 64, NBATCH), blk, DSM64>>>(out);
}

// round 17
// speedup vs baseline: 1.4660x; 1.0297x over previous
#include <cuda_runtime.h>
#include <cuda_bf16.h>
#include <cstdint>

// B=2, M=2048, HID=1024, NH=16, D=64.  Reference has NO softmax =>
//   G_b = h_b^T h_b (symmetric);  T_b = Wk G_b;  S_bh = T_h Wv_h^T;
//   U_b[:,hD:+D] = Wq_h^T S_bh;  Ct_b = Wo U_b^T;  out_b = h_b Ct_b^T.
// All big GEMMs: D = A * B^T, K-major, mma.sync bf16x3
// (A*B ~= Ah*Bh + Ah*Bl + Al*Bh).  R16 ncu: tensor pipe only 47.9% busy at
// 1 CTA/SM -> stall-bound.  This round: every GEMM launch gets >=2 CTAs/SM:
// T/Ct/out use 64x64 tiles (512/512/1024 CTAs, ~3 CTAs/SM), G uses
// split-K 4 (288 CTAs of K=512, 2 CTAs/SM).

#define HIDD   1024
#define MSEQ   2048
#define NBATCH 2
#define NHEAD  16
#define DHEAD  64

typedef __nv_bfloat16 bf16;

// ---------------- device scratch ----------------
__device__ bf16 g_hh[NBATCH * MSEQ * HIDD], g_hl[NBATCH * MSEQ * HIDD];
__device__ bf16 g_hTh[NBATCH * HIDD * MSEQ], g_hTl[NBATCH * HIDD * MSEQ];
__device__ bf16 g_wkh[HIDD * HIDD], g_wkl[HIDD * HIDD];
__device__ bf16 g_woh[HIDD * HIDD], g_wol[HIDD * HIDD];
__device__ float g_Gp[8 * HIDD * HIDD];               // [s*2+b] fp32 partials
__device__ bf16 g_Gh[NBATCH * HIDD * HIDD], g_Gl[NBATCH * HIDD * HIDD];
__device__ float g_T[NBATCH * HIDD * HIDD];
__device__ float g_S[NBATCH * NHEAD * DHEAD * DHEAD];
__device__ bf16 g_Uh[NBATCH * HIDD * HIDD], g_Ul[NBATCH * HIDD * HIDD];
__device__ bf16 g_Cth[NBATCH * HIDD * HIDD], g_Ctl[NBATCH * HIDD * HIDD];

// ---------------- helpers ----------------
__device__ __forceinline__ void split2(float x, bf16& hi, bf16& lo) {
    hi = __float2bfloat16(x);
    lo = __float2bfloat16(x - __bfloat162float(hi));
}

__device__ __forceinline__ uint32_t swz(uint32_t off) {
    return off ^ ((off >> 3) & 0x30);
}

__device__ __forceinline__ void ldsm4(uint32_t* r, uint32_t sa) {
    asm volatile("ldmatrix.sync.aligned.m8n8.x4.shared.b16 {%0,%1,%2,%3}, [%4];"
                 : "=r"(r[0]), "=r"(r[1]), "=r"(r[2]), "=r"(r[3]) : "r"(sa));
}

__device__ __forceinline__ void mma_bf16(float* d, const uint32_t* a,
                                         uint32_t b0, uint32_t b1) {
    asm volatile(
        "mma.sync.aligned.m16n8k16.row.col.f32.bf16.bf16.f32 "
        "{%0,%1,%2,%3}, {%4,%5,%6,%7}, {%8,%9}, {%0,%1,%2,%3};"
        : "+f"(d[0]), "+f"(d[1]), "+f"(d[2]), "+f"(d[3])
        : "r"(a[0]), "r"(a[1]), "r"(a[2]), "r"(a[3]), "r"(b0), "r"(b1));
}

__device__ __forceinline__ void cp16(uint32_t d, const void* s) {
    asm volatile("cp.async.cg.shared.global [%0], [%1], 16;" :: "r"(d), "l"(s));
}

// ---------------- split fp32 -> (hi, lo) bf16 planes ----------------
__global__ __launch_bounds__(256)
void split_kernel(const float4* __restrict__ x, __nv_bfloat162* __restrict__ hi,
                  __nv_bfloat162* __restrict__ lo, int n4) {
    int i = blockIdx.x * 256 + threadIdx.x;
    if (i >= n4) return;
    float4 v = x[i];
    bf16 h0, l0, h1, l1, h2, l2, h3, l3;
    split2(v.x, h0, l0); split2(v.y, h1, l1);
    split2(v.z, h2, l2); split2(v.w, h3, l3);
    hi[2 * i]     = __nv_bfloat162(h0, h1);
    hi[2 * i + 1] = __nv_bfloat162(h2, h3);
    lo[2 * i]     = __nv_bfloat162(l0, l1);
    lo[2 * i + 1] = __nv_bfloat162(l2, l3);
}

// ------- transpose + split: h -> hT planes [b][k][m] AND h planes ----------
__global__ __launch_bounds__(256)
void tsplit_kernel(const float* __restrict__ h) {
    __shared__ float t[32][33];
    const int b = blockIdx.z;
    const int k0 = blockIdx.x * 32, m0 = blockIdx.y * 32;
    const int col = threadIdx.x & 31, rr = threadIdx.x >> 5;

    const float* hp = h + ((size_t)b * MSEQ + m0) * HIDD + k0;
#pragma unroll
    for (int s = 0; s < 4; s++)
        t[rr + s * 8][col] = hp[(size_t)(rr + s * 8) * HIDD + col];
    __syncthreads();

    const size_t nb = ((size_t)b * MSEQ + m0) * HIDD + k0;
#pragma unroll
    for (int s = 0; s < 4; s++) {
        int mr = rr + s * 8;
        bf16 hi, lo;
        split2(t[mr][col], hi, lo);
        g_hh[nb + (size_t)mr * HIDD + col] = hi;
        g_hl[nb + (size_t)mr * HIDD + col] = lo;
    }
    const size_t ob = ((size_t)b * HIDD + k0) * MSEQ + m0;
#pragma unroll
    for (int s = 0; s < 4; s++) {
        int kr = rr + s * 8;
        bf16 hi, lo;
        split2(t[col][kr], hi, lo);
        g_hTh[ob + (size_t)kr * MSEQ + col] = hi;
        g_hTl[ob + (size_t)kr * MSEQ + col] = lo;
    }
}

// -------- G kernel: 128x128 triangular tiles, split-K 4, bf16x3 ------------
// z = s*2 + b, s in 0..3, K=512 per split.  2 CTAs/SM at 288 CTAs.
#define TILE_B 8192
#define BUF_B  (4 * TILE_B)
#define DSM_SIZE (2 * BUF_B + 256)

__device__ __forceinline__ void stage(uint32_t sb, const bf16* g, int ld, int tid) {
#pragma unroll
    for (int i = 0; i < 2; i++) {
        int idx = tid + 256 * i;
        int r = idx >> 2;
        int c = (idx & 3) * 16;
        cp16(sb + swz((uint32_t)(r * 64 + c)),
             (const char*)g + (size_t)r * (ld * 2) + c);
    }
}

__global__ __launch_bounds__(256, 2)
void gemm_g(const bf16* __restrict__ Ah, const bf16* __restrict__ Al,
            float* __restrict__ Cf, int K)
{
    extern __shared__ char dyn[];
    uint32_t dbase = (uint32_t)__cvta_generic_to_shared(dyn);
    dbase = (dbase + 255u) & ~255u;

    const size_t MH = (size_t)MSEQ * HIDD;
    const size_t HH = (size_t)HIDD * HIDD;
    size_t o = (size_t)(blockIdx.z & 1) * MH + (size_t)(blockIdx.z >> 1) * K;
    Ah += o; Al += o;
    Cf += (size_t)blockIdx.z * HH;

    int t = blockIdx.x, i = 0;
    while (t >= 8 - i) { t -= 8 - i; i++; }
    const int bm = i * 128, bn = (i + t) * 128;

    const int tid = threadIdx.x;
    const int lane = tid & 31;
    const int wid = tid >> 5;
    const int wm = (wid >> 2) * 64;
    const int wn = (wid & 3) * 32;

    float acc[4][4][4];
#pragma unroll
    for (int mi = 0; mi < 4; mi++)
#pragma unroll
        for (int ni = 0; ni < 4; ni++)
#pragma unroll
            for (int r = 0; r < 4; r++) acc[mi][ni][r] = 0.0f;

    const bf16* Am  = Ah + (size_t)bm * MSEQ;
    const bf16* Alm = Al + (size_t)bm * MSEQ;
    const bf16* Bm  = Ah + (size_t)bn * MSEQ;
    const bf16* Blm = Al + (size_t)bn * MSEQ;

    const int NIT = K / 32;

    stage(dbase,              Am,  MSEQ, tid);
    stage(dbase + TILE_B,     Alm, MSEQ, tid);
    stage(dbase + 2 * TILE_B, Bm,  MSEQ, tid);
    stage(dbase + 3 * TILE_B, Blm, MSEQ, tid);
    asm volatile("cp.async.commit_group;" ::: "memory");

    for (int it = 0; it < NIT; it++) {
        if (it + 1 < NIT) {
            const uint32_t bo = dbase + ((it + 1) & 1) * BUF_B;
            const int k0 = (it + 1) * 32;
            stage(bo,              Am + k0,  MSEQ, tid);
            stage(bo + TILE_B,     Alm + k0, MSEQ, tid);
            stage(bo + 2 * TILE_B, Bm + k0,  MSEQ, tid);
            stage(bo + 3 * TILE_B, Blm + k0, MSEQ, tid);
            asm volatile("cp.async.commit_group;" ::: "memory");
            asm volatile("cp.async.wait_group 1;" ::: "memory");
        } else {
            asm volatile("cp.async.wait_group 0;" ::: "memory");
        }
        __syncthreads();

        const uint32_t bo = dbase + (it & 1) * BUF_B;
        const int rlane = lane & 15;
        const int kbyte = (lane >> 4) * 16;
#pragma unroll
        for (int kk = 0; kk < 2; kk++) {
            const uint32_t cbyte = kk * 32 + kbyte;
            uint32_t bH[2][4], bL[2][4];
#pragma unroll
            for (int nb = 0; nb < 2; nb++) {
                uint32_t off = (uint32_t)((wn + nb * 16 + rlane) * 64) + cbyte;
                ldsm4(bH[nb], bo + 2 * TILE_B + swz(off));
                ldsm4(bL[nb], bo + 3 * TILE_B + swz(off));
            }
#pragma unroll
            for (int half = 0; half < 2; half++) {
                uint32_t aH[2][4], aL[2][4];
#pragma unroll
                for (int m2 = 0; m2 < 2; m2++) {
                    uint32_t off =
                        (uint32_t)((wm + (half * 2 + m2) * 16 + rlane) * 64) + cbyte;
                    ldsm4(aH[m2], bo + swz(off));
                    ldsm4(aL[m2], bo + TILE_B + swz(off));
                }
#pragma unroll
                for (int m2 = 0; m2 < 2; m2++)
#pragma unroll
                    for (int ni = 0; ni < 4; ni++) {
                        const int nb = ni >> 1, sub = ni & 1;
                        mma_bf16(acc[half * 2 + m2][ni], aH[m2],
                                 bH[nb][sub], bH[nb][sub + 2]);
                    }
#pragma unroll
                for (int m2 = 0; m2 < 2; m2++)
#pragma unroll
                    for (int ni = 0; ni < 4; ni++) {
                        const int nb = ni >> 1, sub = ni & 1;
                        mma_bf16(acc[half * 2 + m2][ni], aH[m2],
                                 bL[nb][sub], bL[nb][sub + 2]);
                    }
#pragma unroll
                for (int m2 = 0; m2 < 2; m2++)
#pragma unroll
                    for (int ni = 0; ni < 4; ni++) {
                        const int nb = ni >> 1, sub = ni & 1;
                        mma_bf16(acc[half * 2 + m2][ni], aL[m2],
                                 bH[nb][sub], bH[nb][sub + 2]);
                    }
            }
        }
        __syncthreads();
    }

    const int g = lane >> 2;
    const int c2 = (lane & 3) * 2;
#pragma unroll
    for (int mi = 0; mi < 4; mi++) {
#pragma unroll
        for (int ni = 0; ni < 4; ni++) {
            int row0 = bm + wm + mi * 16 + g;
            int col  = bn + wn + ni * 8 + c2;
            float* a = acc[mi][ni];
            *(float2*)(Cf + (size_t)row0 * HIDD + col)       = make_float2(a[0], a[1]);
            *(float2*)(Cf + (size_t)(row0 + 8) * HIDD + col) = make_float2(a[2], a[3]);
        }
    }
}

// -------- general 64x64 bf16x3 GEMM: D = A * B^T, K=1024, ld=1024 ----------
// 8 warps as 2(M) x 4(N), warp tile 32x16.  ~3 CTAs/SM.
#define TILE64_B 4096
#define BUF64_B  (4 * TILE64_B)
#define DSM64    (2 * BUF64_B + 256)

__device__ __forceinline__ void stage64(uint32_t sb, const bf16* g, int tid) {
    int r = tid >> 2;
    int c = (tid & 3) * 16;
    cp16(sb + swz((uint32_t)(r * 64 + c)),
         (const char*)g + (size_t)r * (HIDD * 2) + c);
}

template <bool OSPLIT>
__global__ __launch_bounds__(256)
void gemm64(const bf16* __restrict__ Ah, const bf16* __restrict__ Al,
            const bf16* __restrict__ Bh, const bf16* __restrict__ Bl,
            float* __restrict__ Cf, bf16* __restrict__ Ch, bf16* __restrict__ Cl,
            size_t sA, size_t sB, size_t sC)
{
    extern __shared__ char dyn[];
    uint32_t dbase = (uint32_t)__cvta_generic_to_shared(dyn);
    dbase = (dbase + 255u) & ~255u;

    const int b = blockIdx.z;
    const int bm = blockIdx.y * 64;
    const int bn = blockIdx.x * 64;

    const bf16* Am  = Ah + (size_t)b * sA + (size_t)bm * HIDD;
    const bf16* Alm = Al + (size_t)b * sA + (size_t)bm * HIDD;
    const bf16* Bm  = Bh + (size_t)b * sB + (size_t)bn * HIDD;
    const bf16* Blm = Bl + (size_t)b * sB + (size_t)bn * HIDD;
    if (OSPLIT) { Ch += (size_t)b * sC; Cl += (size_t)b * sC; }
    else        { Cf += (size_t)b * sC; }

    const int tid = threadIdx.x;
    const int lane = tid & 31;
    const int wid = tid >> 5;
    const int wm = (wid >> 2) * 32;
    const int wn = (wid & 3) * 16;

    float acc[2][2][4];
#pragma unroll
    for (int mi = 0; mi < 2; mi++)
#pragma unroll
        for (int ni = 0; ni < 2; ni++)
#pragma unroll
            for (int r = 0; r < 4; r++) acc[mi][ni][r] = 0.0f;

    const int NIT = HIDD / 32;

    stage64(dbase,                Am,  tid);
    stage64(dbase + TILE64_B,     Alm, tid);
    stage64(dbase + 2 * TILE64_B, Bm,  tid);
    stage64(dbase + 3 * TILE64_B, Blm, tid);
    asm volatile("cp.async.commit_group;" ::: "memory");

    for (int it = 0; it < NIT; it++) {
        if (it + 1 < NIT) {
            const uint32_t bo = dbase + ((it + 1) & 1) * BUF64_B;
            const int k0 = (it + 1) * 32;
            stage64(bo,                Am + k0,  tid);
            stage64(bo + TILE64_B,     Alm + k0, tid);
            stage64(bo + 2 * TILE64_B, Bm + k0,  tid);
            stage64(bo + 3 * TILE64_B, Blm + k0, tid);
            asm volatile("cp.async.commit_group;" ::: "memory");
            asm volatile("cp.async.wait_group 1;" ::: "memory");
        } else {
            asm volatile("cp.async.wait_group 0;" ::: "memory");
        }
        __syncthreads();

        const uint32_t bo = dbase + (it & 1) * BUF64_B;
        const int rlane = lane & 15;
        const int kbyte = (lane >> 4) * 16;
#pragma unroll
        for (int kk = 0; kk < 2; kk++) {
            const uint32_t cbyte = kk * 32 + kbyte;
            uint32_t bH[4], bL[4], aH[2][4], aL[2][4];
            {
                uint32_t off = (uint32_t)((wn + rlane) * 64) + cbyte;
                ldsm4(bH, bo + 2 * TILE64_B + swz(off));
                ldsm4(bL, bo + 3 * TILE64_B + swz(off));
            }
#pragma unroll
            for (int mi = 0; mi < 2; mi++) {
                uint32_t off = (uint32_t)((wm + mi * 16 + rlane) * 64) + cbyte;
                ldsm4(aH[mi], bo + swz(off));
                ldsm4(aL[mi], bo + TILE64_B + swz(off));
            }
#pragma unroll
            for (int mi = 0; mi < 2; mi++)
#pragma unroll
                for (int ni = 0; ni < 2; ni++)
                    mma_bf16(acc[mi][ni], aH[mi], bH[ni], bH[ni + 2]);
#pragma unroll
            for (int mi = 0; mi < 2; mi++)
#pragma unroll
                for (int ni = 0; ni < 2; ni++)
                    mma_bf16(acc[mi][ni], aH[mi], bL[ni], bL[ni + 2]);
#pragma unroll
            for (int mi = 0; mi < 2; mi++)
#pragma unroll
                for (int ni = 0; ni < 2; ni++)
                    mma_bf16(acc[mi][ni], aL[mi], bH[ni], bH[ni + 2]);
        }
        __syncthreads();
    }

    const int g = lane >> 2;
    const int c2 = (lane & 3) * 2;
#pragma unroll
    for (int mi = 0; mi < 2; mi++) {
#pragma unroll
        for (int ni = 0; ni < 2; ni++) {
            int row0 = bm + wm + mi * 16 + g;
            int col  = bn + wn + ni * 8 + c2;
            float* a = acc[mi][ni];
            if (OSPLIT) {
                bf16 h0, l0, h1, l1;
                split2(a[0], h0, l0); split2(a[1], h1, l1);
                *(__nv_bfloat162*)(Ch + (size_t)row0 * HIDD + col) = __nv_bfloat162(h0, h1);
                *(__nv_bfloat162*)(Cl + (size_t)row0 * HIDD + col) = __nv_bfloat162(l0, l1);
                split2(a[2], h0, l0); split2(a[3], h1, l1);
                *(__nv_bfloat162*)(Ch + (size_t)(row0 + 8) * HIDD + col) = __nv_bfloat162(h0, h1);
                *(__nv_bfloat162*)(Cl + (size_t)(row0 + 8) * HIDD + col) = __nv_bfloat162(l0, l1);
            } else {
                *(float2*)(Cf + (size_t)row0 * HIDD + col)       = make_float2(a[0], a[1]);
                *(float2*)(Cf + (size_t)(row0 + 8) * HIDD + col) = make_float2(a[2], a[3]);
            }
        }
    }
}

// ---------------- G combine: sum 4 split-K partials, bf16 planes, mirror ---
#define GCOMB_SMEM (128 * 129 * 4)
__global__ __launch_bounds__(256)
void gcomb_kernel()
{
    extern __shared__ float ts[];
    const int b = blockIdx.y;
    int t = blockIdx.x, i = 0;
    while (t >= 8 - i) { t -= 8 - i; i++; }
    const int j = i + t;
    const size_t HH = (size_t)HIDD * HIDD;
    const int tid = threadIdx.x;

    const size_t toff = (size_t)(i * 128) * HIDD + j * 128;
    for (int idx = tid; idx < 128 * 32; idx += 256) {
        int r = idx >> 5, c4 = (idx & 31) * 4;
        float4 s0 = *(const float4*)(g_Gp + (size_t)b * HH       + toff + (size_t)r * HIDD + c4);
        float4 s1 = *(const float4*)(g_Gp + (size_t)(2 + b) * HH + toff + (size_t)r * HIDD + c4);
        float4 s2 = *(const float4*)(g_Gp + (size_t)(4 + b) * HH + toff + (size_t)r * HIDD + c4);
        float4 s3 = *(const float4*)(g_Gp + (size_t)(6 + b) * HH + toff + (size_t)r * HIDD + c4);
        ts[r * 129 + c4 + 0] = (s0.x + s1.x) + (s2.x + s3.x);
        ts[r * 129 + c4 + 1] = (s0.y + s1.y) + (s2.y + s3.y);
        ts[r * 129 + c4 + 2] = (s0.z + s1.z) + (s2.z + s3.z);
        ts[r * 129 + c4 + 3] = (s0.w + s1.w) + (s2.w + s3.w);
    }
    __syncthreads();

    bf16* Gh = g_Gh + (size_t)b * HH;
    bf16* Gl = g_Gl + (size_t)b * HH;

    {
        const size_t base = (size_t)(i * 128) * HIDD + j * 128;
        for (int idx = tid; idx < 128 * 64; idx += 256) {
            int r = idx >> 6, c2 = (idx & 63) * 2;
            bf16 h0, l0, h1, l1;
            split2(ts[r * 129 + c2], h0, l0);
            split2(ts[r * 129 + c2 + 1], h1, l1);
            *(__nv_bfloat162*)(Gh + base + (size_t)r * HIDD + c2) = __nv_bfloat162(h0, h1);
            *(__nv_bfloat162*)(Gl + base + (size_t)r * HIDD + c2) = __nv_bfloat162(l0, l1);
        }
    }
    if (i != j) {
        const size_t base = (size_t)(j * 128) * HIDD + i * 128;
        for (int idx = tid; idx < 128 * 64; idx += 256) {
            int r = idx >> 6, c2 = (idx & 63) * 2;
            bf16 h0, l0, h1, l1;
            split2(ts[c2 * 129 + r], h0, l0);
            split2(ts[(c2 + 1) * 129 + r], h1, l1);
            *(__nv_bfloat162*)(Gh + base + (size_t)r * HIDD + c2) = __nv_bfloat162(h0, h1);
            *(__nv_bfloat162*)(Gl + base + (size_t)r * HIDD + c2) = __nv_bfloat162(l0, l1);
        }
    }
}

// ---------------- S: S_bh[i,j] = sum_q T_b[h*64+i,q] * Wv[h*64+j,q] --------
__global__ __launch_bounds__(256)
void st_kernel(const float* __restrict__ Wv)
{
    const int bh = blockIdx.x;
    const int b = bh >> 4, h = bh & 15;
    const float* Tp = g_T + (size_t)b * HIDD * HIDD + (size_t)(h * DHEAD) * HIDD;
    const float* Wp = Wv + (size_t)(h * DHEAD) * HIDD;

    __shared__ float Ts[32][68];
    __shared__ float Ws[32][68];

    const int tid = threadIdx.x;
    const int i4 = (tid & 15) * 4, j4 = (tid >> 4) * 4;

    float acc[4][4];
#pragma unroll
    for (int i = 0; i < 4; i++)
#pragma unroll
        for (int j = 0; j < 4; j++) acc[i][j] = 0.0f;

    for (int k0 = 0; k0 < HIDD; k0 += 32) {
#pragma unroll
        for (int s = 0; s < 2; s++) {
            int idx = tid + 256 * s;
            int i = idx >> 3;
            int c4 = (idx & 7) * 4;
            float4 tv = *(const float4*)(Tp + (size_t)i * HIDD + k0 + c4);
            Ts[c4 + 0][i] = tv.x; Ts[c4 + 1][i] = tv.y;
            Ts[c4 + 2][i] = tv.z; Ts[c4 + 3][i] = tv.w;
            float4 wv = *(const float4*)(Wp + (size_t)i * HIDD + k0 + c4);
            Ws[c4 + 0][i] = wv.x; Ws[c4 + 1][i] = wv.y;
            Ws[c4 + 2][i] = wv.z; Ws[c4 + 3][i] = wv.w;
        }
        __syncthreads();
#pragma unroll 8
        for (int kk = 0; kk < 32; kk++) {
            float tf[4], vf[4];
            *(float4*)tf = *(const float4*)&Ts[kk][i4];
            *(float4*)vf = *(const float4*)&Ws[kk][j4];
#pragma unroll
            for (int i = 0; i < 4; i++)
#pragma unroll
                for (int j = 0; j < 4; j++) acc[i][j] += tf[i] * vf[j];
        }
        __syncthreads();
    }

    float* Sp = g_S + (size_t)bh * (DHEAD * DHEAD);
#pragma unroll
    for (int i = 0; i < 4; i++)
        *(float4*)(Sp + (size_t)(i4 + i) * DHEAD + j4) =
            make_float4(acc[i][0], acc[i][1], acc[i][2], acc[i][3]);
}

// ---------------- U: U[b][k][h*64+j] = sum_i Wq[h*64+i][k]*S_bh[i][j] ------
__global__ __launch_bounds__(256)
void u_kernel(const float* __restrict__ Wq)
{
    const int bh = blockIdx.x;
    const int b = bh >> 4, h = bh & 15;
    const int k = blockIdx.y * 256 + threadIdx.x;
    const int j0 = blockIdx.z * 32;

    __shared__ float Ss[DHEAD][32];
    for (int e = threadIdx.x; e < DHEAD * 32; e += 256) {
        int i = e >> 5, j = e & 31;
        Ss[i][j] = g_S[(size_t)bh * (DHEAD * DHEAD) + i * DHEAD + j0 + j];
    }
    __syncthreads();

    float acc[32];
#pragma unroll
    for (int j = 0; j < 32; j++) acc[j] = 0.0f;

#pragma unroll 4
    for (int i = 0; i < DHEAD; i++) {
        float w = Wq[(size_t)(h * DHEAD + i) * HIDD + k];
#pragma unroll
        for (int j = 0; j < 32; j += 4) {
            float4 sv = *(const float4*)&Ss[i][j];
            acc[j + 0] += w * sv.x; acc[j + 1] += w * sv.y;
            acc[j + 2] += w * sv.z; acc[j + 3] += w * sv.w;
        }
    }

    size_t base = ((size_t)b * HIDD + k) * HIDD + h * DHEAD + j0;
#pragma unroll
    for (int j = 0; j < 32; j += 2) {
        bf16 h0, l0, h1, l1;
        split2(acc[j], h0, l0); split2(acc[j + 1], h1, l1);
        *(__nv_bfloat162*)(g_Uh + base + j) = __nv_bfloat162(h0, h1);
        *(__nv_bfloat162*)(g_Ul + base + j) = __nv_bfloat162(l0, l1);
    }
}

// ---------------- launch ----------------
extern "C" void kernel_launch(void* const* d_in, const int* in_sizes, int n_in,
                              void* d_out, int out_size)
{
    const float* h  = (const float*)d_in[0];
    // d_in[1] = key_pe: dead branch in reference, unused.
    const float* Wq = (const float*)d_in[2];
    const float* Wk = (const float*)d_in[3];
    const float* Wv = (const float*)d_in[4];
    const float* Wo = (const float*)d_in[5];
    float* out = (float*)d_out;

    bf16 *hh, *hl, *hTh, *hTl, *wkh, *wkl, *woh, *wol, *Gh, *Gl, *Uh, *Ul, *Cth, *Ctl;
    float *Gpp, *Tp;
    cudaGetSymbolAddress((void**)&hh, g_hh);   cudaGetSymbolAddress((void**)&hl, g_hl);
    cudaGetSymbolAddress((void**)&hTh, g_hTh); cudaGetSymbolAddress((void**)&hTl, g_hTl);
    cudaGetSymbolAddress((void**)&wkh, g_wkh); cudaGetSymbolAddress((void**)&wkl, g_wkl);
    cudaGetSymbolAddress((void**)&woh, g_woh); cudaGetSymbolAddress((void**)&wol, g_wol);
    cudaGetSymbolAddress((void**)&Gpp, g_Gp);
    cudaGetSymbolAddress((void**)&Gh, g_Gh);   cudaGetSymbolAddress((void**)&Gl, g_Gl);
    cudaGetSymbolAddress((void**)&Tp, g_T);
    cudaGetSymbolAddress((void**)&Uh, g_Uh);   cudaGetSymbolAddress((void**)&Ul, g_Ul);
    cudaGetSymbolAddress((void**)&Cth, g_Cth); cudaGetSymbolAddress((void**)&Ctl, g_Ctl);

    cudaFuncSetAttribute(gemm_g,        cudaFuncAttributeMaxDynamicSharedMemorySize, DSM_SIZE);
    cudaFuncSetAttribute(gemm64<false>, cudaFuncAttributeMaxDynamicSharedMemorySize, DSM64);
    cudaFuncSetAttribute(gemm64<true>,  cudaFuncAttributeMaxDynamicSharedMemorySize, DSM64);
    cudaFuncSetAttribute(gcomb_kernel,  cudaFuncAttributeMaxDynamicSharedMemorySize, GCOMB_SMEM);

    const dim3 blk(256);
    const size_t HH = (size_t)HIDD * HIDD;
    const size_t MH = (size_t)MSEQ * HIDD;
    const int nw4 = (HIDD * HIDD) / 4;

    // input prep (tsplit also emits the non-transposed h planes)
    tsplit_kernel<<<dim3(HIDD / 32, MSEQ / 32, NBATCH), blk>>>(h);
    split_kernel<<<(nw4 + 255) / 256, blk>>>((const float4*)Wk,
        (__nv_bfloat162*)wkh, (__nv_bfloat162*)wkl, nw4);
    split_kernel<<<(nw4 + 255) / 256, blk>>>((const float4*)Wo,
        (__nv_bfloat162*)woh, (__nv_bfloat162*)wol, nw4);

    // G partials: triangular tiles (36), split-K 4 (z = s*2+b, K=512) -> fp32
    gemm_g<<<dim3(36, 1, 8), blk, DSM_SIZE>>>(hTh, hTl, Gpp, 512);

    // combine 4 partials, split to bf16 planes, mirror lower triangle
    gcomb_kernel<<<dim3(36, NBATCH), blk, GCOMB_SMEM>>>();

    // T_b = Wk * G_b (G symmetric => A*B^T form) -> fp32, 64x64 tiles
    gemm64<false><<<dim3(HIDD / 64, HIDD / 64, NBATCH), blk, DSM64>>>(
        wkh, wkl, Gh, Gl, Tp, nullptr, nullptr, 0, HH, HH);

    // S_bh = T_h * Wv_h^T (fp32, small)
    st_kernel<<<dim3(NBATCH * NHEAD), blk>>>(Wv);

    // U (fp32 compute, bf16 hi/lo planes out)
    u_kernel<<<dim3(NBATCH * NHEAD, HIDD / 256, 2), blk>>>(Wq);

    // Ct_b[n,k] = sum_j Wo[n,j] U_b[k,j] -> bf16 planes, 64x64 tiles
    gemm64<true><<<dim3(HIDD / 64, HIDD / 64, NBATCH), blk, DSM64>>>(
        woh, wol, Uh, Ul, nullptr, Cth, Ctl, 0, HH, HH);

    // out_b[m,n] = sum_k h_b[m,k] Ct_b[n,k]  (64x64 tiles)
    gemm64<false><<<dim3(HIDD / 64, MSEQ / 64, NBATCH), blk, DSM64>>>(
        hh, hl, Cth, Ctl, out, nullptr, nullptr, MH, HH, MH);
}